// round 8
// baseline (speedup 1.0000x reference)
#include <cuda_runtime.h>

#define HH 256
#define WW 256
#define MAXSLICES 64
#define TPC 16              // CTAs (16-col tiles) per slice
#define CSTRIDE 17          // u16 row stride for g tile (odd half-warp bank shift: conflict-free)

// ---- device globals (allocation-free scratch / rendezvous state) ----
// g_bits: packed mask, rewritten every replay (deterministic).
// g_tk_pack / g_tk_max: monotonic tickets across graph replays -> reset-free.
// g_pmax: plain-overwritten by the same CTA each replay.
__device__ unsigned g_bits[MAXSLICES * (HH * WW / 32)];   // 2048 words/slice
__device__ int g_tk_pack[MAXSLICES];
__device__ int g_tk_max[MAXSLICES];
__device__ int g_pmax[MAXSLICES][TPC];

// ============== fallback pre-pack (only if grid exceeds residency) =========
__global__ void __launch_bounds__(256) k_pack(const float* __restrict__ in)
{
    const int base = blockIdx.x * 2048 + threadIdx.x;
    #pragma unroll
    for (int i = 0; i < 8; i++) {
        int n = base + i * 256;
        bool m = (in[n] != 0.0f);
        unsigned b = __ballot_sync(0xffffffffu, m);
        if ((threadIdx.x & 31) == 0) g_bits[n >> 5] = b;
    }
}

__device__ __forceinline__ void spin_until(volatile int* p, int target)
{
    while (*p < target) __nanosleep(32);
}

// ================= mega-kernel ================
// CTA = (slice, 16-col tile); 256 threads = 16 cols x 16 row-groups of 16 rows.
// do_pack=1: phase 0 packs this CTA's 16 rows, rendezvous, then proceed.
__global__ void __launch_bounds__(256, 6)
wdt_fused(const float* __restrict__ in, float* __restrict__ out, int do_pack)
{
    __shared__ unsigned       bm[HH * 8];           // 8192 B: slice bitmask; reused as d2 park
    __shared__ unsigned short gs[HH * CSTRIDE];     // 8704 B: g tile
    __shared__ int   s_red;
    __shared__ int   s_m2;
    __shared__ float s_rinv;

    const int slice = blockIdx.x >> 4;
    const int ct    = blockIdx.x & 15;
    const int t     = threadIdx.x;
    float* oslab = out + (size_t)slice * (HH * WW) + ct * 16;

    if (t == 0) s_red = 0;

    // ---- phase 0: pack this CTA's 16 rows, then per-slice rendezvous ----
    // Progress-safe even if capacity < grid: CTAs are scheduled ~in bid order,
    // so fully-resident slices complete and free slots for pending CTAs.
    if (do_pack) {
        const int base = slice * (HH * WW) + ct * 4096 + t;   // rows [ct*16, ct*16+16)
        #pragma unroll
        for (int i = 0; i < 16; i++) {
            int n = base + i * 256;
            bool m = (in[n] != 0.0f);
            unsigned b = __ballot_sync(0xffffffffu, m);
            if ((t & 31) == 0) g_bits[n >> 5] = b;
        }
        __threadfence();                 // publish stores before ticket
        __syncthreads();
        if (t == 0) {
            int tk = atomicAdd(&g_tk_pack[slice], 1);     // monotonic
            int target = (tk & ~(TPC - 1)) + TPC;         // my replay's group of 16
            spin_until(&g_tk_pack[slice], target);
            __threadfence();
        }
        __syncthreads();
    }

    // ---- phase 1: load packed slice bitmask via L2 (coalesced, coherent) ----
    {
        const unsigned* src = g_bits + slice * 2048;
        #pragma unroll
        for (int i = 0; i < 8; i++) bm[i * 256 + t] = __ldcg(&src[i * 256 + t]);
    }
    __syncthreads();

    // ---- phase 2: horizontal nearest-zero distance for this tile's 16 cols ----
    const int col  = t & 15;                  // column within tile
    const int gcol = ct * 16 + col;           // global column
    const int wi = gcol >> 5, j = gcol & 31;
    const unsigned maskL = (j == 0)  ? 0u : (0xffffffffu >> (32 - j));
    const unsigned maskR = (j == 31) ? 0u : (0xffffffffu << (j + 1));
    const int q0 = (t >> 4) * 16;             // this thread's 16 rows

    for (int r = q0; r < q0 + 16; r++) {
        const unsigned* row = bm + r * 8;
        unsigned mi = row[wi];
        int gv = 0;
        if ((mi >> j) & 1) {
            int dl = 512, dr = 512;           // BIG = H + W (matches reference clamp)
            unsigned y = (~mi) & maskL;
            if (y) dl = j - (31 - __clz(y));
            else {
                #pragma unroll
                for (int k = 6; k >= 0; k--) if (k < wi) {
                    unsigned iv = ~row[k];
                    if (iv) { dl = j - (31 - __clz(iv)) + 32 * (wi - k); break; }
                }
            }
            y = (~mi) & maskR;
            if (y) dr = __ffs(y) - 1 - j;
            else {
                #pragma unroll
                for (int k = 1; k < 8; k++) if (k > wi) {
                    unsigned iv = ~row[k];
                    if (iv) { dr = __ffs(iv) - 1 - j + 32 * (k - wi); break; }
                }
            }
            gv = min(dl, dr);
        }
        gs[r * CSTRIDE + col] = (unsigned short)gv;
    }
    __syncthreads();          // phase 2 done; bm is dead -> becomes the d2 park

    // ---- phase 3: exact vertical min-plus (shrinking radius) ----
    // d2[q] = min_r' g[r']^2 + (q-r')^2; start r'=q, stop when dr^2 >= best: exact.
    int colmax = 0;
    unsigned pair = 0;
    #pragma unroll
    for (int k = 0; k < 16; k++) {
        int q = q0 + k;
        int gv = gs[q * CSTRIDE + col];
        int best = gv * gv;
        for (int dr = 1; dr * dr < best; dr++) {
            int drsq = dr * dr;
            int u = q - dr, v = q + dr;
            if (u >= 0) { int c = gs[u * CSTRIDE + col]; c = c * c + drsq; if (c < best) best = c; }
            if (v < HH) { int c = gs[v * CSTRIDE + col]; c = c * c + drsq; if (c < best) best = c; }
        }
        if (best > colmax) colmax = best;
        unsigned pb = (unsigned)min(best, 65535);   // exact whenever the slice has any zero
        if ((k & 1) == 0) pair = pb;
        else              bm[(k >> 1) * 256 + t] = pair | (pb << 16);
    }

    // ---- phase 4: CTA max, then TPC-way reset-free rendezvous ----
    #pragma unroll
    for (int off = 16; off; off >>= 1)
        colmax = max(colmax, __shfl_xor_sync(0xffffffffu, colmax, off));
    if ((t & 31) == 0) atomicMax(&s_red, colmax);
    __syncthreads();

    if (t == 0) {
        g_pmax[slice][ct] = s_red;                  // plain store each replay
        __threadfence();
        int tk = atomicAdd(&g_tk_max[slice], 1);    // monotonic ticket
        int target = (tk & ~(TPC - 1)) + TPC;
        spin_until(&g_tk_max[slice], target);
        __threadfence();
        int m2 = 0;
        #pragma unroll
        for (int i = 0; i < TPC; i++) m2 = max(m2, __ldcg(&g_pmax[slice][i]));
        s_m2 = m2;
        s_rinv = (m2 > 0) ? rsqrtf((float)m2) : 0.0f;
    }
    __syncthreads();

    // ---- phase 5: normalized output, written exactly once ----
    const float rinv = s_rinv;
    if (s_m2 > 0) {
        #pragma unroll
        for (int i = 0; i < 8; i++) {
            unsigned w = bm[i * 256 + t];
            int q = q0 + 2 * i;
            oslab[q * WW + col]       = 1.0f - sqrtf((float)(w & 0xffffu)) * rinv;
            oslab[(q + 1) * WW + col] = 1.0f - sqrtf((float)(w >> 16)) * rinv;
        }
    } else {
        // whole slice background: dt == 0 everywhere, reference outputs dt (= 0)
        #pragma unroll
        for (int i = 0; i < 16; i++) oslab[(q0 + i) * WW + col] = 0.0f;
    }
}

extern "C" void kernel_launch(void* const* d_in, const int* in_sizes, int n_in,
                              void* d_out, int out_size)
{
    const float* in = (const float*)d_in[0];
    float* out = (float*)d_out;

    int slices = in_sizes[0] / (HH * WW);   // 48 for the reference shapes
    if (slices > MAXSLICES) slices = MAXSLICES;

    // Pin max shared-memory carveout so 6 CTAs/SM (6 x 16.9KB = 101.5KB) is
    // never smem-limited. Host-side attribute set; capture-legal.
    cudaFuncSetAttribute(wdt_fused, cudaFuncAttributePreferredSharedMemoryCarveout, 100);

    // launch_bounds(256,6) => capacity 148*6 = 888 resident CTAs >= grid (768)
    // for the bench -> all CTAs co-resident -> rendezvous trivially safe; and
    // even if capacity were lower, bid-ordered scheduling keeps it progress-safe.
    if (slices * TPC <= 888) {
        wdt_fused<<<slices * TPC, 256>>>(in, out, 1);
    } else {
        k_pack<<<slices * 32, 256>>>(in);
        wdt_fused<<<slices * TPC, 256>>>(in, out, 0);
    }
}